// round 1
// baseline (speedup 1.0000x reference)
#include <cuda_runtime.h>
#include <math.h>

// ---------------- problem constants ----------------
#define BB      2048
#define NN      32
#define DD      6
#define OBSD    17
#define HH      256
#define IND     23          // OBS + D
#define BN      (BB*NN)     // 65536
#define NSTEPS  10
#define LRv     0.1f
#define LIMITv  1.0f
#define LOG_NP1v 3.4965075614664802f   // log(33)

// ---------------- tiling ----------------
#define ROWS  16            // rows per score-kernel block
#define PITCH 20            // shared pitch (floats) per hidden unit, pad to break conflicts

// ---------------- device scratch ----------------
__device__ float g_a[BN*DD];
__device__ float g_score[BN*DD];
__device__ float g_logp[BN];
__device__ float g_W2T[HH*HH];

// 16 FMAs against a pitch-PITCH shared row, loaded as 4x float4 (broadcast)
#define FMA16(acc, baseptr, w) do {                                        \
  const float4* _h4 = (const float4*)(baseptr);                            \
  float4 _v0 = _h4[0], _v1 = _h4[1], _v2 = _h4[2], _v3 = _h4[3];           \
  acc[0]  = fmaf(_v0.x, (w), acc[0]);  acc[1]  = fmaf(_v0.y, (w), acc[1]); \
  acc[2]  = fmaf(_v0.z, (w), acc[2]);  acc[3]  = fmaf(_v0.w, (w), acc[3]); \
  acc[4]  = fmaf(_v1.x, (w), acc[4]);  acc[5]  = fmaf(_v1.y, (w), acc[5]); \
  acc[6]  = fmaf(_v1.z, (w), acc[6]);  acc[7]  = fmaf(_v1.w, (w), acc[7]); \
  acc[8]  = fmaf(_v2.x, (w), acc[8]);  acc[9]  = fmaf(_v2.y, (w), acc[9]); \
  acc[10] = fmaf(_v2.z, (w), acc[10]); acc[11] = fmaf(_v2.w, (w), acc[11]);\
  acc[12] = fmaf(_v3.x, (w), acc[12]); acc[13] = fmaf(_v3.y, (w), acc[13]);\
  acc[14] = fmaf(_v3.z, (w), acc[14]); acc[15] = fmaf(_v3.w, (w), acc[15]);\
} while (0)

// ---------------- init: copy a, zero logp, transpose W2 ----------------
__global__ void __launch_bounds__(256) init_kernel(const float* __restrict__ a_in,
                                                   const float* __restrict__ W2) {
  int idx = blockIdx.x * 256 + threadIdx.x;
  if (idx < BN*DD) g_a[idx] = a_in[idx];
  if (idx < BN)    g_logp[idx] = 0.f;
  if (idx < HH*HH) {
    int i = idx / HH, j = idx - i*HH;
    g_W2T[j*HH + i] = W2[idx];
  }
}

// ---------------- score = d/dX sum q1(obs, X) ----------------
// Block: 256 threads, ROWS rows. One thread per hidden unit in the H loops.
__global__ void __launch_bounds__(256) score_kernel(
    const float* __restrict__ obs, const float* __restrict__ W1,
    const float* __restrict__ b1,  const float* __restrict__ W2,
    const float* __restrict__ b2,  const float* __restrict__ W3)
{
  __shared__ __align__(16) float sx[ROWS][24];          // input rows (23 used)
  __shared__ __align__(16) float sh1[HH*PITCH];         // h1 (relu'd), later dh1, layout [h][r]
  __shared__ __align__(16) float sdh2[HH*PITCH];        // dh2, layout [j][r]
  const int tid  = threadIdx.x;
  const int row0 = blockIdx.x * ROWS;

  // load inputs (obs || a)
  for (int p = tid; p < ROWS*IND; p += 256) {
    int r = p / IND, k = p - r*IND;
    int gr = row0 + r;
    sx[r][k] = (k < OBSD) ? obs[gr*OBSD + k] : g_a[gr*DD + (k - OBSD)];
  }
  __syncthreads();

  // ---- layer 1 forward: h1 = relu(x @ W1 + b1) ----
  {
    float acc[ROWS];
    const float bb = b1[tid];
    #pragma unroll
    for (int r = 0; r < ROWS; r++) acc[r] = bb;
    #pragma unroll
    for (int k = 0; k < IND; k++) {
      float w = W1[k*HH + tid];
      #pragma unroll
      for (int r = 0; r < ROWS; r++) acc[r] = fmaf(sx[r][k], w, acc[r]);
    }
    #pragma unroll
    for (int r = 0; r < ROWS; r++) sh1[tid*PITCH + r] = fmaxf(acc[r], 0.f);
  }
  __syncthreads();

  // ---- layer 2 forward (z2) -> dh2 = (z2>0) ? W3 : 0 ----
  {
    float acc[ROWS];
    const float bb = b2[tid];
    #pragma unroll
    for (int r = 0; r < ROWS; r++) acc[r] = bb;
    #pragma unroll 2
    for (int i = 0; i < HH; i++) {
      float w = W2[i*HH + tid];
      FMA16(acc, &sh1[i*PITCH], w);
    }
    const float w3 = W3[tid];
    #pragma unroll
    for (int r = 0; r < ROWS; r++)
      sdh2[tid*PITCH + r] = (acc[r] > 0.f) ? w3 : 0.f;
  }
  __syncthreads();

  // ---- dh1 = (h1>0) .* (W2 @ dh2) ; overwrite sh1 with dh1 ----
  {
    float acc[ROWS];
    #pragma unroll
    for (int r = 0; r < ROWS; r++) acc[r] = 0.f;
    #pragma unroll 2
    for (int j = 0; j < HH; j++) {
      float w = g_W2T[j*HH + tid];
      FMA16(acc, &sdh2[j*PITCH], w);
    }
    float dh1v[ROWS];
    #pragma unroll
    for (int r = 0; r < ROWS; r++)
      dh1v[r] = (sh1[tid*PITCH + r] > 0.f) ? acc[r] : 0.f;
    __syncthreads();
    #pragma unroll
    for (int r = 0; r < ROWS; r++) sh1[tid*PITCH + r] = dh1v[r];
  }
  __syncthreads();

  // ---- dX[d] = sum_i W1[17+d][i] * dh1[i] ; warp w handles rows {w, w+8} ----
  {
    const int warp = tid >> 5, lane = tid & 31;
    float a0[DD], a1[DD];
    #pragma unroll
    for (int d = 0; d < DD; d++) { a0[d] = 0.f; a1[d] = 0.f; }
    #pragma unroll 2
    for (int i = lane; i < HH; i += 32) {
      float v0 = sh1[i*PITCH + warp];
      float v1 = sh1[i*PITCH + warp + 8];
      #pragma unroll
      for (int d = 0; d < DD; d++) {
        float w = W1[(OBSD + d)*HH + i];
        a0[d] = fmaf(w, v0, a0[d]);
        a1[d] = fmaf(w, v1, a1[d]);
      }
    }
    #pragma unroll
    for (int d = 0; d < DD; d++) {
      #pragma unroll
      for (int off = 16; off; off >>= 1) {
        a0[d] += __shfl_xor_sync(0xffffffffu, a0[d], off);
        a1[d] += __shfl_xor_sync(0xffffffffu, a1[d], off);
      }
    }
    if (lane == 0) {
      #pragma unroll
      for (int d = 0; d < DD; d++) {
        g_score[(row0 + warp)*DD + d]     = a0[d];
        g_score[(row0 + warp + 8)*DD + d] = a1[d];
      }
    }
  }
}

// ---------------- SVGD update per batch ----------------
__global__ void __launch_bounds__(256) svgd_kernel() {
  __shared__ float sX[NN*DD];
  __shared__ float sS[NN*DD];
  __shared__ float sD2[NN*NN];
  __shared__ float sSort[NN*NN];
  __shared__ float sGamma;
  const int tid = threadIdx.x;
  const int b   = blockIdx.x;

  for (int p = tid; p < NN*DD; p += 256) {
    sX[p] = g_a[b*NN*DD + p];
    sS[p] = g_score[b*NN*DD + p];
  }
  __syncthreads();

  // pairwise squared distances
  for (int p = tid; p < NN*NN; p += 256) {
    int i = p >> 5, j = p & 31;
    float d2 = 0.f;
    #pragma unroll
    for (int d = 0; d < DD; d++) {
      float df = sX[i*DD + d] - sX[j*DD + d];
      d2 = fmaf(df, df, d2);
    }
    sD2[p]  = d2;
    sSort[p] = d2;
  }

  // bitonic sort of 1024 values (exact median index 511, matches jnp.sort)
  for (int k = 2; k <= NN*NN; k <<= 1) {
    for (int j = k >> 1; j > 0; j >>= 1) {
      __syncthreads();
      for (int p = tid; p < NN*NN; p += 256) {
        int q = p ^ j;
        if (q > p) {
          float va = sSort[p], vb = sSort[q];
          bool up = ((p & k) == 0);
          if (up ? (va > vb) : (va < vb)) { sSort[p] = vb; sSort[q] = va; }
        }
      }
    }
  }
  __syncthreads();
  if (tid == 0) {
    float med = sSort[(NN*NN - 1) / 2];           // index 511
    sGamma = 1.f / (1e-8f + med / LOG_NP1v);      // 1/(1e-8 + 2h), h = med/(2 log(N+1))
  }
  __syncthreads();
  const float gamma = sGamma;

  // warp w handles rows i = 4w..4w+3; lane = particle j
  const int warp = tid >> 5, lane = tid & 31;
  float xj[DD], sj[DD];
  #pragma unroll
  for (int d = 0; d < DD; d++) { xj[d] = sX[lane*DD + d]; sj[d] = sS[lane*DD + d]; }

  #pragma unroll
  for (int ii = 0; ii < 4; ii++) {
    const int i = warp*4 + ii;
    float d2 = sD2[i*NN + lane];
    float K  = expf(-gamma * d2);
    float t4 = 0.f;
    float c[DD];
    #pragma unroll
    for (int d = 0; d < DD; d++) {
      float df = sX[i*DD + d] - xj[d];
      t4 = fmaf(df, sj[d], t4);
      c[d] = K * fmaf(2.f*gamma, df, sj[d]);   // K*(s_j + 2*gamma*diff) -> phi
    }
    float l4 = K * t4;                              // -> line_4 (missing -2g/N factor)
    float l5 = K * fmaf(2.f*gamma, d2, -(float)DD); // -> line_5 (missing -2g/N factor)
    #pragma unroll
    for (int off = 16; off; off >>= 1) {
      #pragma unroll
      for (int d = 0; d < DD; d++) c[d] += __shfl_xor_sync(0xffffffffu, c[d], off);
      l4 += __shfl_xor_sync(0xffffffffu, l4, off);
      l5 += __shfl_xor_sync(0xffffffffu, l5, off);
    }
    if (lane == 0) {
      const float scale = -2.f * gamma / (float)NN;
      g_logp[b*NN + i] -= LRv * (scale * (l4 + l5));
      const int base = (b*NN + i)*DD;
      #pragma unroll
      for (int d = 0; d < DD; d++) {
        float av = sX[i*DD + d] + LRv * (c[d] / (float)NN);
        av = fminf(fmaxf(av, -LIMITv), LIMITv);
        g_a[base + d] = av;
      }
    }
  }
}

// ---------------- finalize: out = [a (BN*D) | logp (B*N)] ----------------
__global__ void __launch_bounds__(256) finalize_kernel(float* __restrict__ out, int out_size) {
  int idx = blockIdx.x * 256 + threadIdx.x;
  if (idx >= out_size) return;
  if (idx < BN*DD) {
    out[idx] = g_a[idx];
  } else {
    int k = idx - BN*DD;
    if (k < BN) out[idx] = g_logp[k];
  }
}

// ---------------- launch ----------------
extern "C" void kernel_launch(void* const* d_in, const int* in_sizes, int n_in,
                              void* d_out, int out_size) {
  const float* obs = (const float*)d_in[0];
  const float* a   = (const float*)d_in[1];
  const float* W1  = (const float*)d_in[2];
  const float* b1  = (const float*)d_in[3];
  const float* W2  = (const float*)d_in[4];
  const float* b2  = (const float*)d_in[5];
  const float* W3  = (const float*)d_in[6];
  // d_in[7] = b3: gradient of sum wrt X does not depend on b3
  float* out = (float*)d_out;

  init_kernel<<<(BN*DD + 255)/256, 256>>>(a, W2);
  for (int s = 0; s < NSTEPS; s++) {
    score_kernel<<<BN/ROWS, 256>>>(obs, W1, b1, W2, b2, W3);
    svgd_kernel<<<BB, 256>>>();
  }
  finalize_kernel<<<(out_size + 255)/256, 256>>>(out, out_size);
}

// round 2
// speedup vs baseline: 1.2936x; 1.2936x over previous
#include <cuda_runtime.h>
#include <math.h>

// ---------------- problem constants ----------------
#define BB      2048
#define NN      32
#define DD      6
#define OBSD    17
#define HH      256
#define IND     23          // OBS + D
#define BN      (BB*NN)     // 65536
#define NSTEPS  10
#define LRv     0.1f
#define LIMITv  1.0f
#define LOG_NP1v 3.4965075614664802f   // log(33)

// ---------------- tiling ----------------
#define ROWS  16            // rows per score-kernel block
#define PITCH 20            // shared pitch (floats) per hidden unit
#define SXP   16            // pitch of transposed input tile

typedef unsigned long long u64;

__device__ __forceinline__ u64 pack2(float lo, float hi) {
  u64 r; asm("mov.b64 %0, {%1, %2};" : "=l"(r) : "f"(lo), "f"(hi)); return r;
}
__device__ __forceinline__ u64 dup2(float v) { return pack2(v, v); }
__device__ __forceinline__ void unpack2(u64 v, float& lo, float& hi) {
  asm("mov.b64 {%0, %1}, %2;" : "=f"(lo), "=f"(hi) : "l"(v));
}
__device__ __forceinline__ void ffma2(u64& d, u64 a, u64 b) {
  asm("fma.rn.f32x2 %0, %1, %2, %0;" : "+l"(d) : "l"(a), "l"(b));
}

// ---------------- device scratch ----------------
__device__ float g_a[BN*DD];
__device__ float g_score[BN*DD];
__device__ float g_logp[BN];
__device__ float g_W2T[HH*HH];

// ---------------- init: copy a, zero logp, transpose W2 ----------------
__global__ void __launch_bounds__(256) init_kernel(const float* __restrict__ a_in,
                                                   const float* __restrict__ W2) {
  int idx = blockIdx.x * 256 + threadIdx.x;
  if (idx < BN*DD) g_a[idx] = a_in[idx];
  if (idx < BN)    g_logp[idx] = 0.f;
  if (idx < HH*HH) {
    int i = idx / HH, j = idx - i*HH;
    g_W2T[j*HH + i] = W2[idx];
  }
}

// ---------------- score = d/dX sum q1(obs, X) ----------------
// 256 threads, ROWS=16 rows per block.
// Hot loops: thread handles 2 output units x 8 rows, packed f32x2 FMAs.
__global__ void __launch_bounds__(256) score_kernel(
    const float* __restrict__ obs, const float* __restrict__ W1,
    const float* __restrict__ b1,  const float* __restrict__ W2,
    const float* __restrict__ b2,  const float* __restrict__ W3)
{
  __shared__ __align__(16) float sxT[IND*SXP];   // input, transposed: [k][r]
  __shared__ __align__(16) float sh1[HH*PITCH];  // h1 (relu'd), later dh1: [h][r]
  __shared__ __align__(16) float sdh2[HH*PITCH]; // dh2: [j][r]
  const int tid  = threadIdx.x;
  const int row0 = blockIdx.x * ROWS;

  // load inputs (obs || a), transposed
  for (int p = tid; p < ROWS*IND; p += 256) {
    int r = p / IND, k = p - r*IND;
    int gr = row0 + r;
    sxT[k*SXP + r] = (k < OBSD) ? obs[gr*OBSD + k] : g_a[gr*DD + (k - OBSD)];
  }
  __syncthreads();

  // ---- layer 1 forward: h1 = relu(x @ W1 + b1); unit=tid, 16 rows as 8 f32x2 ----
  {
    u64 acc[8];
    const u64 bb = dup2(b1[tid]);
    #pragma unroll
    for (int q = 0; q < 8; q++) acc[q] = bb;
    #pragma unroll
    for (int k = 0; k < IND; k++) {
      const u64 w = dup2(W1[k*HH + tid]);
      const u64* xp = (const u64*)&sxT[k*SXP];
      #pragma unroll
      for (int q = 0; q < 8; q++) ffma2(acc[q], xp[q], w);
    }
    #pragma unroll
    for (int q = 0; q < 8; q++) {
      float lo, hi; unpack2(acc[q], lo, hi);
      float2 o; o.x = fmaxf(lo, 0.f); o.y = fmaxf(hi, 0.f);
      *(float2*)&sh1[tid*PITCH + 2*q] = o;
    }
  }
  __syncthreads();

  // ---- layer 2 forward (z2) -> dh2 = (z2>0) ? W3 : 0 ----
  const int jj = tid & 127;        // unit pair index
  const int j0 = jj << 1;          // units j0, j0+1
  const int rh = tid >> 7;         // row half
  const int rb = rh << 3;          // row base (0 or 8)
  {
    u64 a0[4], a1[4];
    {
      const float2 bb = *(const float2*)&b2[j0];
      const u64 ba = dup2(bb.x), bbv = dup2(bb.y);
      #pragma unroll
      for (int q = 0; q < 4; q++) { a0[q] = ba; a1[q] = bbv; }
    }
    #pragma unroll 2
    for (int i = 0; i < HH; i++) {
      const float2 w = *(const float2*)&W2[i*HH + j0];
      const u64 wa = dup2(w.x), wb = dup2(w.y);
      const u64* hp = (const u64*)&sh1[i*PITCH + rb];
      const u64 h0 = hp[0], h1 = hp[1], h2 = hp[2], h3 = hp[3];
      ffma2(a0[0], h0, wa); ffma2(a0[1], h1, wa); ffma2(a0[2], h2, wa); ffma2(a0[3], h3, wa);
      ffma2(a1[0], h0, wb); ffma2(a1[1], h1, wb); ffma2(a1[2], h2, wb); ffma2(a1[3], h3, wb);
    }
    const float2 w3 = *(const float2*)&W3[j0];
    #pragma unroll
    for (int q = 0; q < 4; q++) {
      float lo, hi;
      unpack2(a0[q], lo, hi);
      float2 o0; o0.x = (lo > 0.f) ? w3.x : 0.f; o0.y = (hi > 0.f) ? w3.x : 0.f;
      *(float2*)&sdh2[j0*PITCH + rb + 2*q] = o0;
      unpack2(a1[q], lo, hi);
      float2 o1; o1.x = (lo > 0.f) ? w3.y : 0.f; o1.y = (hi > 0.f) ? w3.y : 0.f;
      *(float2*)&sdh2[(j0+1)*PITCH + rb + 2*q] = o1;
    }
  }
  __syncthreads();

  // ---- dh1 = (h1>0) .* (W2 @ dh2); units i0,i0+1, rows rb..rb+7; write back into sh1 ----
  {
    const int i0 = j0;
    u64 a0[4], a1[4];
    #pragma unroll
    for (int q = 0; q < 4; q++) { a0[q] = 0ull; a1[q] = 0ull; }
    #pragma unroll 2
    for (int j = 0; j < HH; j++) {
      const float2 w = *(const float2*)&g_W2T[j*HH + i0];
      const u64 wa = dup2(w.x), wb = dup2(w.y);
      const u64* dp = (const u64*)&sdh2[j*PITCH + rb];
      const u64 d0 = dp[0], d1 = dp[1], d2 = dp[2], d3 = dp[3];
      ffma2(a0[0], d0, wa); ffma2(a0[1], d1, wa); ffma2(a0[2], d2, wa); ffma2(a0[3], d3, wa);
      ffma2(a1[0], d0, wb); ffma2(a1[1], d1, wb); ffma2(a1[2], d2, wb); ffma2(a1[3], d3, wb);
    }
    // mask by h1>0 and write back (each thread touches only its own sh1 slots)
    #pragma unroll
    for (int q = 0; q < 4; q++) {
      float2 h = *(const float2*)&sh1[i0*PITCH + rb + 2*q];
      float lo, hi; unpack2(a0[q], lo, hi);
      float2 o; o.x = (h.x > 0.f) ? lo : 0.f; o.y = (h.y > 0.f) ? hi : 0.f;
      *(float2*)&sh1[i0*PITCH + rb + 2*q] = o;
      h = *(const float2*)&sh1[(i0+1)*PITCH + rb + 2*q];
      unpack2(a1[q], lo, hi);
      o.x = (h.x > 0.f) ? lo : 0.f; o.y = (h.y > 0.f) ? hi : 0.f;
      *(float2*)&sh1[(i0+1)*PITCH + rb + 2*q] = o;
    }
  }
  __syncthreads();

  // ---- dX[d] = sum_i W1[17+d][i] * dh1[i]; warp w handles rows {w, w+8} ----
  {
    const int warp = tid >> 5, lane = tid & 31;
    float a0[DD], a1[DD];
    #pragma unroll
    for (int d = 0; d < DD; d++) { a0[d] = 0.f; a1[d] = 0.f; }
    #pragma unroll 2
    for (int i = lane; i < HH; i += 32) {
      float v0 = sh1[i*PITCH + warp];
      float v1 = sh1[i*PITCH + warp + 8];
      #pragma unroll
      for (int d = 0; d < DD; d++) {
        float w = W1[(OBSD + d)*HH + i];
        a0[d] = fmaf(w, v0, a0[d]);
        a1[d] = fmaf(w, v1, a1[d]);
      }
    }
    #pragma unroll
    for (int d = 0; d < DD; d++) {
      #pragma unroll
      for (int off = 16; off; off >>= 1) {
        a0[d] += __shfl_xor_sync(0xffffffffu, a0[d], off);
        a1[d] += __shfl_xor_sync(0xffffffffu, a1[d], off);
      }
    }
    if (lane == 0) {
      #pragma unroll
      for (int d = 0; d < DD; d++) {
        g_score[(row0 + warp)*DD + d]     = a0[d];
        g_score[(row0 + warp + 8)*DD + d] = a1[d];
      }
    }
  }
}

// ---------------- SVGD update per batch ----------------
__global__ void __launch_bounds__(256) svgd_kernel() {
  __shared__ float sX[NN*DD];
  __shared__ float sS[NN*DD];
  __shared__ float sD2[NN*NN];
  __shared__ float sSort[NN*NN];
  __shared__ float sGamma;
  const int tid = threadIdx.x;
  const int b   = blockIdx.x;

  for (int p = tid; p < NN*DD; p += 256) {
    sX[p] = g_a[b*NN*DD + p];
    sS[p] = g_score[b*NN*DD + p];
  }
  __syncthreads();

  // pairwise squared distances
  for (int p = tid; p < NN*NN; p += 256) {
    int i = p >> 5, j = p & 31;
    float d2 = 0.f;
    #pragma unroll
    for (int d = 0; d < DD; d++) {
      float df = sX[i*DD + d] - sX[j*DD + d];
      d2 = fmaf(df, df, d2);
    }
    sD2[p]   = d2;
    sSort[p] = d2;
  }

  // bitonic sort of 1024 values (exact median index 511)
  for (int k = 2; k <= NN*NN; k <<= 1) {
    for (int j = k >> 1; j > 0; j >>= 1) {
      __syncthreads();
      for (int p = tid; p < NN*NN; p += 256) {
        int q = p ^ j;
        if (q > p) {
          float va = sSort[p], vb = sSort[q];
          bool up = ((p & k) == 0);
          if (up ? (va > vb) : (va < vb)) { sSort[p] = vb; sSort[q] = va; }
        }
      }
    }
  }
  __syncthreads();
  if (tid == 0) {
    float med = sSort[(NN*NN - 1) / 2];
    sGamma = 1.f / (1e-8f + med / LOG_NP1v);
  }
  __syncthreads();
  const float gamma = sGamma;

  const int warp = tid >> 5, lane = tid & 31;
  float xj[DD], sj[DD];
  #pragma unroll
  for (int d = 0; d < DD; d++) { xj[d] = sX[lane*DD + d]; sj[d] = sS[lane*DD + d]; }

  #pragma unroll
  for (int ii = 0; ii < 4; ii++) {
    const int i = warp*4 + ii;
    float d2 = sD2[i*NN + lane];
    float K  = expf(-gamma * d2);
    float t4 = 0.f;
    float c[DD];
    #pragma unroll
    for (int d = 0; d < DD; d++) {
      float df = sX[i*DD + d] - xj[d];
      t4 = fmaf(df, sj[d], t4);
      c[d] = K * fmaf(2.f*gamma, df, sj[d]);
    }
    float l4 = K * t4;
    float l5 = K * fmaf(2.f*gamma, d2, -(float)DD);
    #pragma unroll
    for (int off = 16; off; off >>= 1) {
      #pragma unroll
      for (int d = 0; d < DD; d++) c[d] += __shfl_xor_sync(0xffffffffu, c[d], off);
      l4 += __shfl_xor_sync(0xffffffffu, l4, off);
      l5 += __shfl_xor_sync(0xffffffffu, l5, off);
    }
    if (lane == 0) {
      const float scale = -2.f * gamma / (float)NN;
      g_logp[b*NN + i] -= LRv * (scale * (l4 + l5));
      const int base = (b*NN + i)*DD;
      #pragma unroll
      for (int d = 0; d < DD; d++) {
        float av = sX[i*DD + d] + LRv * (c[d] / (float)NN);
        av = fminf(fmaxf(av, -LIMITv), LIMITv);
        g_a[base + d] = av;
      }
    }
  }
}

// ---------------- finalize: out = [a (BN*D) | logp (B*N)] ----------------
__global__ void __launch_bounds__(256) finalize_kernel(float* __restrict__ out, int out_size) {
  int idx = blockIdx.x * 256 + threadIdx.x;
  if (idx >= out_size) return;
  if (idx < BN*DD) {
    out[idx] = g_a[idx];
  } else {
    int k = idx - BN*DD;
    if (k < BN) out[idx] = g_logp[k];
  }
}

// ---------------- launch ----------------
extern "C" void kernel_launch(void* const* d_in, const int* in_sizes, int n_in,
                              void* d_out, int out_size) {
  const float* obs = (const float*)d_in[0];
  const float* a   = (const float*)d_in[1];
  const float* W1  = (const float*)d_in[2];
  const float* b1  = (const float*)d_in[3];
  const float* W2  = (const float*)d_in[4];
  const float* b2  = (const float*)d_in[5];
  const float* W3  = (const float*)d_in[6];
  float* out = (float*)d_out;

  init_kernel<<<(BN*DD + 255)/256, 256>>>(a, W2);
  for (int s = 0; s < NSTEPS; s++) {
    score_kernel<<<BN/ROWS, 256>>>(obs, W1, b1, W2, b2, W3);
    svgd_kernel<<<BB, 256>>>();
  }
  finalize_kernel<<<(out_size + 255)/256, 256>>>(out, out_size);
}

// round 3
// speedup vs baseline: 1.5132x; 1.1698x over previous
#include <cuda_runtime.h>
#include <math.h>

// ---------------- problem constants ----------------
#define BB      2048
#define NN      32
#define DD      6
#define OBSD    17
#define HH      256
#define IND     23          // OBS + D
#define BN      (BB*NN)     // 65536
#define NSTEPS  10
#define LRv     0.1f
#define LIMITv  1.0f
#define LOG_NP1v 3.4965075614664802f   // log(33)

// ---------------- tiling ----------------
#define ROWS  16            // rows per score-kernel block
#define TPB   128           // threads per score block
#define PITCH 18            // shared pitch (floats) per hidden unit (u64-aligned)
#define SXP   16            // pitch of transposed input tile

typedef unsigned long long u64;

__device__ __forceinline__ u64 pack2(float lo, float hi) {
  u64 r; asm("mov.b64 %0, {%1, %2};" : "=l"(r) : "f"(lo), "f"(hi)); return r;
}
__device__ __forceinline__ u64 dup2(float v) { return pack2(v, v); }
__device__ __forceinline__ void unpack2(u64 v, float& lo, float& hi) {
  asm("mov.b64 {%0, %1}, %2;" : "=f"(lo), "=f"(hi) : "l"(v));
}
__device__ __forceinline__ void ffma2(u64& d, u64 a, u64 b) {
  asm("fma.rn.f32x2 %0, %1, %2, %0;" : "+l"(d) : "l"(a), "l"(b));
}

// ---------------- device scratch ----------------
__device__ float g_a[BN*DD];
__device__ float g_score[BN*DD];
__device__ float g_logp[BN];
__device__ float g_W2T[HH*HH];

// ---------------- init: copy a, zero logp, transpose W2 ----------------
__global__ void __launch_bounds__(256) init_kernel(const float* __restrict__ a_in,
                                                   const float* __restrict__ W2) {
  int idx = blockIdx.x * 256 + threadIdx.x;
  if (idx < BN*DD) g_a[idx] = a_in[idx];
  if (idx < BN)    g_logp[idx] = 0.f;
  if (idx < HH*HH) {
    int i = idx / HH, j = idx - i*HH;
    g_W2T[j*HH + i] = W2[idx];
  }
}

// ---------------- score = d/dX sum q1(obs, X) ----------------
// 128 threads, 16 rows per block.
// Hot loops: thread = 4 output units x 8 rows (16 FFMA2 per inner iteration).
__global__ void __launch_bounds__(TPB) score_kernel(
    const float* __restrict__ obs, const float* __restrict__ W1,
    const float* __restrict__ b1,  const float* __restrict__ W2,
    const float* __restrict__ b2,  const float* __restrict__ W3)
{
  __shared__ __align__(16) float sxT[IND*SXP];   // input, transposed: [k][r]
  __shared__ __align__(16) float sh1[HH*PITCH];  // h1 (relu'd), later dh1: [h][r]
  __shared__ __align__(16) float sdh2[HH*PITCH]; // dh2: [j][r]
  const int tid  = threadIdx.x;
  const int row0 = blockIdx.x * ROWS;

  // load inputs (obs || a), transposed
  for (int p = tid; p < ROWS*IND; p += TPB) {
    int r = p / IND, k = p - r*IND;
    int gr = row0 + r;
    sxT[k*SXP + r] = (k < OBSD) ? obs[gr*OBSD + k] : g_a[gr*DD + (k - OBSD)];
  }
  __syncthreads();

  // ---- layer 1 forward: h1 = relu(x @ W1 + b1); thread = 2 units x 16 rows ----
  {
    const int j0 = tid << 1;
    u64 a0[8], a1[8];
    {
      const float2 bb = *(const float2*)&b1[j0];
      const u64 ba = dup2(bb.x), bbv = dup2(bb.y);
      #pragma unroll
      for (int q = 0; q < 8; q++) { a0[q] = ba; a1[q] = bbv; }
    }
    #pragma unroll
    for (int k = 0; k < IND; k++) {
      const float2 w = *(const float2*)&W1[k*HH + j0];
      const u64 wa = dup2(w.x), wb = dup2(w.y);
      const u64* xp = (const u64*)&sxT[k*SXP];
      #pragma unroll
      for (int q = 0; q < 8; q++) { ffma2(a0[q], xp[q], wa); ffma2(a1[q], xp[q], wb); }
    }
    #pragma unroll
    for (int q = 0; q < 8; q++) {
      float lo, hi;
      unpack2(a0[q], lo, hi);
      float2 o; o.x = fmaxf(lo, 0.f); o.y = fmaxf(hi, 0.f);
      *(float2*)&sh1[j0*PITCH + 2*q] = o;
      unpack2(a1[q], lo, hi);
      o.x = fmaxf(lo, 0.f); o.y = fmaxf(hi, 0.f);
      *(float2*)&sh1[(j0+1)*PITCH + 2*q] = o;
    }
  }
  __syncthreads();

  // thread mapping for the two big loops: quad q (4 units), row-group g (8 rows)
  const int qd = tid & 63;         // 64 quads
  const int j0 = qd << 2;          // units j0..j0+3
  const int rb = (tid >> 6) << 3;  // row base: 0 or 8

  // ---- layer 2 forward (z2) -> dh2 = (z2>0) ? W3 : 0 ----
  {
    u64 acc[4][4];
    {
      const float4 bb = *(const float4*)&b2[j0];
      const u64 b4[4] = { dup2(bb.x), dup2(bb.y), dup2(bb.z), dup2(bb.w) };
      #pragma unroll
      for (int s = 0; s < 4; s++)
        #pragma unroll
        for (int k = 0; k < 4; k++) acc[s][k] = b4[s];
    }
    #pragma unroll 2
    for (int i = 0; i < HH; i++) {
      const float4 w = *(const float4*)&W2[i*HH + j0];
      const u64 w0 = dup2(w.x), w1 = dup2(w.y), w2v = dup2(w.z), w3v = dup2(w.w);
      const u64* hp = (const u64*)&sh1[i*PITCH + rb];
      const u64 h0 = hp[0], h1 = hp[1], h2 = hp[2], h3 = hp[3];
      ffma2(acc[0][0], h0, w0); ffma2(acc[0][1], h1, w0); ffma2(acc[0][2], h2, w0); ffma2(acc[0][3], h3, w0);
      ffma2(acc[1][0], h0, w1); ffma2(acc[1][1], h1, w1); ffma2(acc[1][2], h2, w1); ffma2(acc[1][3], h3, w1);
      ffma2(acc[2][0], h0, w2v); ffma2(acc[2][1], h1, w2v); ffma2(acc[2][2], h2, w2v); ffma2(acc[2][3], h3, w2v);
      ffma2(acc[3][0], h0, w3v); ffma2(acc[3][1], h1, w3v); ffma2(acc[3][2], h2, w3v); ffma2(acc[3][3], h3, w3v);
    }
    const float4 w3q = *(const float4*)&W3[j0];
    const float w3s[4] = { w3q.x, w3q.y, w3q.z, w3q.w };
    #pragma unroll
    for (int s = 0; s < 4; s++) {
      #pragma unroll
      for (int k = 0; k < 4; k++) {
        float lo, hi; unpack2(acc[s][k], lo, hi);
        float2 o; o.x = (lo > 0.f) ? w3s[s] : 0.f; o.y = (hi > 0.f) ? w3s[s] : 0.f;
        *(float2*)&sdh2[(j0+s)*PITCH + rb + 2*k] = o;
      }
    }
  }
  __syncthreads();

  // ---- dh1 = (h1>0) .* (W2 @ dh2); same 4x8 blocking, write back into sh1 ----
  {
    u64 acc[4][4];
    #pragma unroll
    for (int s = 0; s < 4; s++)
      #pragma unroll
      for (int k = 0; k < 4; k++) acc[s][k] = 0ull;
    #pragma unroll 2
    for (int j = 0; j < HH; j++) {
      const float4 w = *(const float4*)&g_W2T[j*HH + j0];
      const u64 w0 = dup2(w.x), w1 = dup2(w.y), w2v = dup2(w.z), w3v = dup2(w.w);
      const u64* dp = (const u64*)&sdh2[j*PITCH + rb];
      const u64 d0 = dp[0], d1 = dp[1], d2 = dp[2], d3 = dp[3];
      ffma2(acc[0][0], d0, w0); ffma2(acc[0][1], d1, w0); ffma2(acc[0][2], d2, w0); ffma2(acc[0][3], d3, w0);
      ffma2(acc[1][0], d0, w1); ffma2(acc[1][1], d1, w1); ffma2(acc[1][2], d2, w1); ffma2(acc[1][3], d3, w1);
      ffma2(acc[2][0], d0, w2v); ffma2(acc[2][1], d1, w2v); ffma2(acc[2][2], d2, w2v); ffma2(acc[2][3], d3, w2v);
      ffma2(acc[3][0], d0, w3v); ffma2(acc[3][1], d1, w3v); ffma2(acc[3][2], d2, w3v); ffma2(acc[3][3], d3, w3v);
    }
    // mask by h1>0 and write back (slots owned exclusively by this thread now)
    #pragma unroll
    for (int s = 0; s < 4; s++) {
      #pragma unroll
      for (int k = 0; k < 4; k++) {
        float2 h = *(const float2*)&sh1[(j0+s)*PITCH + rb + 2*k];
        float lo, hi; unpack2(acc[s][k], lo, hi);
        float2 o; o.x = (h.x > 0.f) ? lo : 0.f; o.y = (h.y > 0.f) ? hi : 0.f;
        *(float2*)&sh1[(j0+s)*PITCH + rb + 2*k] = o;
      }
    }
  }
  __syncthreads();

  // ---- dX[d] = sum_i W1[17+d][i] * dh1[i]; warp w handles rows {w, w+4, w+8, w+12} ----
  {
    const int warp = tid >> 5, lane = tid & 31;
    float a[4][DD];
    #pragma unroll
    for (int m = 0; m < 4; m++)
      #pragma unroll
      for (int d = 0; d < DD; d++) a[m][d] = 0.f;
    #pragma unroll 2
    for (int i = lane; i < HH; i += 32) {
      float v[4];
      #pragma unroll
      for (int m = 0; m < 4; m++) v[m] = sh1[i*PITCH + warp + 4*m];
      #pragma unroll
      for (int d = 0; d < DD; d++) {
        float w = W1[(OBSD + d)*HH + i];
        #pragma unroll
        for (int m = 0; m < 4; m++) a[m][d] = fmaf(w, v[m], a[m][d]);
      }
    }
    #pragma unroll
    for (int m = 0; m < 4; m++)
      #pragma unroll
      for (int d = 0; d < DD; d++)
        #pragma unroll
        for (int off = 16; off; off >>= 1)
          a[m][d] += __shfl_xor_sync(0xffffffffu, a[m][d], off);
    if (lane == 0) {
      #pragma unroll
      for (int m = 0; m < 4; m++)
        #pragma unroll
        for (int d = 0; d < DD; d++)
          g_score[(row0 + warp + 4*m)*DD + d] = a[m][d];
    }
  }
}

// ---------------- SVGD update per batch ----------------
__global__ void __launch_bounds__(256) svgd_kernel() {
  __shared__ float sX[NN*DD];
  __shared__ float sS[NN*DD];
  __shared__ float sD2[NN*NN];
  __shared__ float sSort[NN*NN];
  __shared__ float sGamma;
  const int tid = threadIdx.x;
  const int b   = blockIdx.x;

  for (int p = tid; p < NN*DD; p += 256) {
    sX[p] = g_a[b*NN*DD + p];
    sS[p] = g_score[b*NN*DD + p];
  }
  __syncthreads();

  // pairwise squared distances
  for (int p = tid; p < NN*NN; p += 256) {
    int i = p >> 5, j = p & 31;
    float d2 = 0.f;
    #pragma unroll
    for (int d = 0; d < DD; d++) {
      float df = sX[i*DD + d] - sX[j*DD + d];
      d2 = fmaf(df, df, d2);
    }
    sD2[p]   = d2;
    sSort[p] = d2;
  }

  // bitonic sort of 1024 values (exact median index 511)
  for (int k = 2; k <= NN*NN; k <<= 1) {
    for (int j = k >> 1; j > 0; j >>= 1) {
      __syncthreads();
      for (int p = tid; p < NN*NN; p += 256) {
        int q = p ^ j;
        if (q > p) {
          float va = sSort[p], vb = sSort[q];
          bool up = ((p & k) == 0);
          if (up ? (va > vb) : (va < vb)) { sSort[p] = vb; sSort[q] = va; }
        }
      }
    }
  }
  __syncthreads();
  if (tid == 0) {
    float med = sSort[(NN*NN - 1) / 2];
    sGamma = 1.f / (1e-8f + med / LOG_NP1v);
  }
  __syncthreads();
  const float gamma = sGamma;

  const int warp = tid >> 5, lane = tid & 31;
  float xj[DD], sj[DD];
  #pragma unroll
  for (int d = 0; d < DD; d++) { xj[d] = sX[lane*DD + d]; sj[d] = sS[lane*DD + d]; }

  #pragma unroll
  for (int ii = 0; ii < 4; ii++) {
    const int i = warp*4 + ii;
    float d2 = sD2[i*NN + lane];
    float K  = expf(-gamma * d2);
    float t4 = 0.f;
    float c[DD];
    #pragma unroll
    for (int d = 0; d < DD; d++) {
      float df = sX[i*DD + d] - xj[d];
      t4 = fmaf(df, sj[d], t4);
      c[d] = K * fmaf(2.f*gamma, df, sj[d]);
    }
    float l4 = K * t4;
    float l5 = K * fmaf(2.f*gamma, d2, -(float)DD);
    #pragma unroll
    for (int off = 16; off; off >>= 1) {
      #pragma unroll
      for (int d = 0; d < DD; d++) c[d] += __shfl_xor_sync(0xffffffffu, c[d], off);
      l4 += __shfl_xor_sync(0xffffffffu, l4, off);
      l5 += __shfl_xor_sync(0xffffffffu, l5, off);
    }
    if (lane == 0) {
      const float scale = -2.f * gamma / (float)NN;
      g_logp[b*NN + i] -= LRv * (scale * (l4 + l5));
      const int base = (b*NN + i)*DD;
      #pragma unroll
      for (int d = 0; d < DD; d++) {
        float av = sX[i*DD + d] + LRv * (c[d] / (float)NN);
        av = fminf(fmaxf(av, -LIMITv), LIMITv);
        g_a[base + d] = av;
      }
    }
  }
}

// ---------------- finalize: out = [a (BN*D) | logp (B*N)] ----------------
__global__ void __launch_bounds__(256) finalize_kernel(float* __restrict__ out, int out_size) {
  int idx = blockIdx.x * 256 + threadIdx.x;
  if (idx >= out_size) return;
  if (idx < BN*DD) {
    out[idx] = g_a[idx];
  } else {
    int k = idx - BN*DD;
    if (k < BN) out[idx] = g_logp[k];
  }
}

// ---------------- launch ----------------
extern "C" void kernel_launch(void* const* d_in, const int* in_sizes, int n_in,
                              void* d_out, int out_size) {
  const float* obs = (const float*)d_in[0];
  const float* a   = (const float*)d_in[1];
  const float* W1  = (const float*)d_in[2];
  const float* b1  = (const float*)d_in[3];
  const float* W2  = (const float*)d_in[4];
  const float* b2  = (const float*)d_in[5];
  const float* W3  = (const float*)d_in[6];
  float* out = (float*)d_out;

  init_kernel<<<(BN*DD + 255)/256, 256>>>(a, W2);
  for (int s = 0; s < NSTEPS; s++) {
    score_kernel<<<BN/ROWS, TPB>>>(obs, W1, b1, W2, b2, W3);
    svgd_kernel<<<BB, 256>>>();
  }
  finalize_kernel<<<(out_size + 255)/256, 256>>>(out, out_size);
}

// round 4
// speedup vs baseline: 1.5171x; 1.0026x over previous
#include <cuda_runtime.h>
#include <math.h>

// ---------------- problem constants ----------------
#define BB      2048
#define NN      32
#define DD      6
#define OBSD    17
#define HH      256
#define IND     23          // OBS + D
#define BN      (BB*NN)     // 65536
#define NSTEPS  10
#define LRv     0.1f
#define LIMITv  1.0f
#define LOG_NP1v 3.4965075614664802f   // log(33)

// ---------------- tiling ----------------
#define ROWS  16            // rows per score-kernel block
#define TPB   128           // threads per score block
#define PITCH 18            // shared pitch (floats) per hidden unit (u64-aligned)
#define SXP   16            // pitch of transposed input tile

typedef unsigned long long u64;

__device__ __forceinline__ u64 pack2(float lo, float hi) {
  u64 r; asm("mov.b64 %0, {%1, %2};" : "=l"(r) : "f"(lo), "f"(hi)); return r;
}
__device__ __forceinline__ u64 dup2(float v) { return pack2(v, v); }
__device__ __forceinline__ void unpack2(u64 v, float& lo, float& hi) {
  asm("mov.b64 {%0, %1}, %2;" : "=f"(lo), "=f"(hi) : "l"(v));
}
__device__ __forceinline__ void ffma2(u64& d, u64 a, u64 b) {
  asm("fma.rn.f32x2 %0, %1, %2, %0;" : "+l"(d) : "l"(a), "l"(b));
}

// ---------------- device scratch ----------------
__device__ float g_a[BN*DD];
__device__ float g_score[BN*DD];
__device__ float g_logp[BN];
__device__ float g_W2T[HH*HH];

// ---------------- init: copy a, zero logp, transpose W2 ----------------
__global__ void __launch_bounds__(256) init_kernel(const float* __restrict__ a_in,
                                                   const float* __restrict__ W2) {
  int idx = blockIdx.x * 256 + threadIdx.x;
  if (idx < BN*DD) g_a[idx] = a_in[idx];
  if (idx < BN)    g_logp[idx] = 0.f;
  if (idx < HH*HH) {
    int i = idx / HH, j = idx - i*HH;
    g_W2T[j*HH + i] = W2[idx];
  }
}

// ---------------- score = d/dX sum q1(obs, X) ----------------
// 128 threads, 16 rows per block.
// Hot loops: thread = 4 output units x 8 rows (16 FFMA2 per inner iteration).
__global__ void __launch_bounds__(TPB) score_kernel(
    const float* __restrict__ obs, const float* __restrict__ W1,
    const float* __restrict__ b1,  const float* __restrict__ W2,
    const float* __restrict__ b2,  const float* __restrict__ W3)
{
  __shared__ __align__(16) float sxT[IND*SXP];   // input, transposed: [k][r]
  __shared__ __align__(16) float sh1[HH*PITCH];  // h1 (relu'd), later dh1: [h][r]
  __shared__ __align__(16) float sdh2[HH*PITCH]; // dh2: [j][r]
  const int tid  = threadIdx.x;
  const int row0 = blockIdx.x * ROWS;

  // load inputs (obs || a), transposed
  for (int p = tid; p < ROWS*IND; p += TPB) {
    int r = p / IND, k = p - r*IND;
    int gr = row0 + r;
    sxT[k*SXP + r] = (k < OBSD) ? obs[gr*OBSD + k] : g_a[gr*DD + (k - OBSD)];
  }
  __syncthreads();

  // ---- layer 1 forward: h1 = relu(x @ W1 + b1); thread = 2 units x 16 rows ----
  {
    const int j0 = tid << 1;
    u64 a0[8], a1[8];
    {
      const float2 bb = *(const float2*)&b1[j0];
      const u64 ba = dup2(bb.x), bbv = dup2(bb.y);
      #pragma unroll
      for (int q = 0; q < 8; q++) { a0[q] = ba; a1[q] = bbv; }
    }
    #pragma unroll
    for (int k = 0; k < IND; k++) {
      const float2 w = *(const float2*)&W1[k*HH + j0];
      const u64 wa = dup2(w.x), wb = dup2(w.y);
      const u64* xp = (const u64*)&sxT[k*SXP];
      #pragma unroll
      for (int q = 0; q < 8; q++) { ffma2(a0[q], xp[q], wa); ffma2(a1[q], xp[q], wb); }
    }
    #pragma unroll
    for (int q = 0; q < 8; q++) {
      float lo, hi;
      unpack2(a0[q], lo, hi);
      float2 o; o.x = fmaxf(lo, 0.f); o.y = fmaxf(hi, 0.f);
      *(float2*)&sh1[j0*PITCH + 2*q] = o;
      unpack2(a1[q], lo, hi);
      o.x = fmaxf(lo, 0.f); o.y = fmaxf(hi, 0.f);
      *(float2*)&sh1[(j0+1)*PITCH + 2*q] = o;
    }
  }
  __syncthreads();

  // thread mapping for the two big loops: quad q (4 units), row-group g (8 rows)
  const int qd = tid & 63;         // 64 quads
  const int j0 = qd << 2;          // units j0..j0+3
  const int rb = (tid >> 6) << 3;  // row base: 0 or 8

  // ---- layer 2 forward (z2) -> dh2 = (z2>0) ? W3 : 0 ----
  {
    u64 acc[4][4];
    {
      const float4 bb = *(const float4*)&b2[j0];
      const u64 b4[4] = { dup2(bb.x), dup2(bb.y), dup2(bb.z), dup2(bb.w) };
      #pragma unroll
      for (int s = 0; s < 4; s++)
        #pragma unroll
        for (int k = 0; k < 4; k++) acc[s][k] = b4[s];
    }
    #pragma unroll 2
    for (int i = 0; i < HH; i++) {
      const float4 w = *(const float4*)&W2[i*HH + j0];
      const u64 w0 = dup2(w.x), w1 = dup2(w.y), w2v = dup2(w.z), w3v = dup2(w.w);
      const u64* hp = (const u64*)&sh1[i*PITCH + rb];
      const u64 h0 = hp[0], h1 = hp[1], h2 = hp[2], h3 = hp[3];
      ffma2(acc[0][0], h0, w0); ffma2(acc[0][1], h1, w0); ffma2(acc[0][2], h2, w0); ffma2(acc[0][3], h3, w0);
      ffma2(acc[1][0], h0, w1); ffma2(acc[1][1], h1, w1); ffma2(acc[1][2], h2, w1); ffma2(acc[1][3], h3, w1);
      ffma2(acc[2][0], h0, w2v); ffma2(acc[2][1], h1, w2v); ffma2(acc[2][2], h2, w2v); ffma2(acc[2][3], h3, w2v);
      ffma2(acc[3][0], h0, w3v); ffma2(acc[3][1], h1, w3v); ffma2(acc[3][2], h2, w3v); ffma2(acc[3][3], h3, w3v);
    }
    const float4 w3q = *(const float4*)&W3[j0];
    const float w3s[4] = { w3q.x, w3q.y, w3q.z, w3q.w };
    #pragma unroll
    for (int s = 0; s < 4; s++) {
      #pragma unroll
      for (int k = 0; k < 4; k++) {
        float lo, hi; unpack2(acc[s][k], lo, hi);
        float2 o; o.x = (lo > 0.f) ? w3s[s] : 0.f; o.y = (hi > 0.f) ? w3s[s] : 0.f;
        *(float2*)&sdh2[(j0+s)*PITCH + rb + 2*k] = o;
      }
    }
  }
  __syncthreads();

  // ---- dh1 = (h1>0) .* (W2 @ dh2); same 4x8 blocking, write back into sh1 ----
  {
    u64 acc[4][4];
    #pragma unroll
    for (int s = 0; s < 4; s++)
      #pragma unroll
      for (int k = 0; k < 4; k++) acc[s][k] = 0ull;
    #pragma unroll 2
    for (int j = 0; j < HH; j++) {
      const float4 w = *(const float4*)&g_W2T[j*HH + j0];
      const u64 w0 = dup2(w.x), w1 = dup2(w.y), w2v = dup2(w.z), w3v = dup2(w.w);
      const u64* dp = (const u64*)&sdh2[j*PITCH + rb];
      const u64 d0 = dp[0], d1 = dp[1], d2 = dp[2], d3 = dp[3];
      ffma2(acc[0][0], d0, w0); ffma2(acc[0][1], d1, w0); ffma2(acc[0][2], d2, w0); ffma2(acc[0][3], d3, w0);
      ffma2(acc[1][0], d0, w1); ffma2(acc[1][1], d1, w1); ffma2(acc[1][2], d2, w1); ffma2(acc[1][3], d3, w1);
      ffma2(acc[2][0], d0, w2v); ffma2(acc[2][1], d1, w2v); ffma2(acc[2][2], d2, w2v); ffma2(acc[2][3], d3, w2v);
      ffma2(acc[3][0], d0, w3v); ffma2(acc[3][1], d1, w3v); ffma2(acc[3][2], d2, w3v); ffma2(acc[3][3], d3, w3v);
    }
    // mask by h1>0 and write back (slots owned exclusively by this thread now)
    #pragma unroll
    for (int s = 0; s < 4; s++) {
      #pragma unroll
      for (int k = 0; k < 4; k++) {
        float2 h = *(const float2*)&sh1[(j0+s)*PITCH + rb + 2*k];
        float lo, hi; unpack2(acc[s][k], lo, hi);
        float2 o; o.x = (h.x > 0.f) ? lo : 0.f; o.y = (h.y > 0.f) ? hi : 0.f;
        *(float2*)&sh1[(j0+s)*PITCH + rb + 2*k] = o;
      }
    }
  }
  __syncthreads();

  // ---- dX[d] = sum_i W1[17+d][i] * dh1[i]; warp w handles rows {w, w+4, w+8, w+12} ----
  {
    const int warp = tid >> 5, lane = tid & 31;
    float a[4][DD];
    #pragma unroll
    for (int m = 0; m < 4; m++)
      #pragma unroll
      for (int d = 0; d < DD; d++) a[m][d] = 0.f;
    #pragma unroll 2
    for (int i = lane; i < HH; i += 32) {
      float v[4];
      #pragma unroll
      for (int m = 0; m < 4; m++) v[m] = sh1[i*PITCH + warp + 4*m];
      #pragma unroll
      for (int d = 0; d < DD; d++) {
        float w = W1[(OBSD + d)*HH + i];
        #pragma unroll
        for (int m = 0; m < 4; m++) a[m][d] = fmaf(w, v[m], a[m][d]);
      }
    }
    #pragma unroll
    for (int m = 0; m < 4; m++)
      #pragma unroll
      for (int d = 0; d < DD; d++)
        #pragma unroll
        for (int off = 16; off; off >>= 1)
          a[m][d] += __shfl_xor_sync(0xffffffffu, a[m][d], off);
    if (lane == 0) {
      #pragma unroll
      for (int m = 0; m < 4; m++)
        #pragma unroll
        for (int d = 0; d < DD; d++)
          g_score[(row0 + warp + 4*m)*DD + d] = a[m][d];
    }
  }
}

// ---------------- SVGD update per batch ----------------
__global__ void __launch_bounds__(256) svgd_kernel() {
  __shared__ float sX[NN*DD];
  __shared__ float sS[NN*DD];
  __shared__ float sD2[NN*NN];
  __shared__ float sSort[NN*NN];
  __shared__ float sGamma;
  const int tid = threadIdx.x;
  const int b   = blockIdx.x;

  for (int p = tid; p < NN*DD; p += 256) {
    sX[p] = g_a[b*NN*DD + p];
    sS[p] = g_score[b*NN*DD + p];
  }
  __syncthreads();

  // pairwise squared distances
  for (int p = tid; p < NN*NN; p += 256) {
    int i = p >> 5, j = p & 31;
    float d2 = 0.f;
    #pragma unroll
    for (int d = 0; d < DD; d++) {
      float df = sX[i*DD + d] - sX[j*DD + d];
      d2 = fmaf(df, df, d2);
    }
    sD2[p]   = d2;
    sSort[p] = d2;
  }

  // bitonic sort of 1024 values (exact median index 511)
  for (int k = 2; k <= NN*NN; k <<= 1) {
    for (int j = k >> 1; j > 0; j >>= 1) {
      __syncthreads();
      for (int p = tid; p < NN*NN; p += 256) {
        int q = p ^ j;
        if (q > p) {
          float va = sSort[p], vb = sSort[q];
          bool up = ((p & k) == 0);
          if (up ? (va > vb) : (va < vb)) { sSort[p] = vb; sSort[q] = va; }
        }
      }
    }
  }
  __syncthreads();
  if (tid == 0) {
    float med = sSort[(NN*NN - 1) / 2];
    sGamma = 1.f / (1e-8f + med / LOG_NP1v);
  }
  __syncthreads();
  const float gamma = sGamma;

  const int warp = tid >> 5, lane = tid & 31;
  float xj[DD], sj[DD];
  #pragma unroll
  for (int d = 0; d < DD; d++) { xj[d] = sX[lane*DD + d]; sj[d] = sS[lane*DD + d]; }

  #pragma unroll
  for (int ii = 0; ii < 4; ii++) {
    const int i = warp*4 + ii;
    float d2 = sD2[i*NN + lane];
    float K  = expf(-gamma * d2);
    float t4 = 0.f;
    float c[DD];
    #pragma unroll
    for (int d = 0; d < DD; d++) {
      float df = sX[i*DD + d] - xj[d];
      t4 = fmaf(df, sj[d], t4);
      c[d] = K * fmaf(2.f*gamma, df, sj[d]);
    }
    float l4 = K * t4;
    float l5 = K * fmaf(2.f*gamma, d2, -(float)DD);
    #pragma unroll
    for (int off = 16; off; off >>= 1) {
      #pragma unroll
      for (int d = 0; d < DD; d++) c[d] += __shfl_xor_sync(0xffffffffu, c[d], off);
      l4 += __shfl_xor_sync(0xffffffffu, l4, off);
      l5 += __shfl_xor_sync(0xffffffffu, l5, off);
    }
    if (lane == 0) {
      const float scale = -2.f * gamma / (float)NN;
      g_logp[b*NN + i] -= LRv * (scale * (l4 + l5));
      const int base = (b*NN + i)*DD;
      #pragma unroll
      for (int d = 0; d < DD; d++) {
        float av = sX[i*DD + d] + LRv * (c[d] / (float)NN);
        av = fminf(fmaxf(av, -LIMITv), LIMITv);
        g_a[base + d] = av;
      }
    }
  }
}

// ---------------- finalize: out = [a (BN*D) | logp (B*N)] ----------------
__global__ void __launch_bounds__(256) finalize_kernel(float* __restrict__ out, int out_size) {
  int idx = blockIdx.x * 256 + threadIdx.x;
  if (idx >= out_size) return;
  if (idx < BN*DD) {
    out[idx] = g_a[idx];
  } else {
    int k = idx - BN*DD;
    if (k < BN) out[idx] = g_logp[k];
  }
}

// ---------------- launch ----------------
extern "C" void kernel_launch(void* const* d_in, const int* in_sizes, int n_in,
                              void* d_out, int out_size) {
  const float* obs = (const float*)d_in[0];
  const float* a   = (const float*)d_in[1];
  const float* W1  = (const float*)d_in[2];
  const float* b1  = (const float*)d_in[3];
  const float* W2  = (const float*)d_in[4];
  const float* b2  = (const float*)d_in[5];
  const float* W3  = (const float*)d_in[6];
  float* out = (float*)d_out;

  init_kernel<<<(BN*DD + 255)/256, 256>>>(a, W2);
  for (int s = 0; s < NSTEPS; s++) {
    score_kernel<<<BN/ROWS, TPB>>>(obs, W1, b1, W2, b2, W3);
    svgd_kernel<<<BB, 256>>>();
  }
  finalize_kernel<<<(out_size + 255)/256, 256>>>(out, out_size);
}